// round 12
// baseline (speedup 1.0000x reference)
#include <cuda_runtime.h>
#include <cstdint>

#define BB 4
#define SS 2048
#define HH 16
#define DD 64
#define DMODEL 1024
#define PITCH 68            // smem row pitch (floats): 68%32=4 -> conflict-free ldmatrix phases
#define SCALE (1.0f/32.0f)  // score / (D/2)

// ---------------- scratch (no runtime allocation allowed) -------------------
__device__ float g_Qp[BB*HH*SS*DD];   // [bh][s][d], tf32-rounded
__device__ float g_Kp[BB*HH*SS*DD];   // [bh][s][d], tf32-rounded
__device__ float g_Vt[BB*HH*DD*SS];   // [bh][d][s] transposed, tf32-rounded
__device__ float g_O [BB*SS*DMODEL];  // [b][s][h*D+d], tf32-rounded
__device__ float g_Wr[DMODEL*DMODEL]; // Wo tf32-rounded

// ---------------- helpers ---------------------------------------------------
__device__ __forceinline__ uint32_t smem_to_u32(const void* p) {
    uint32_t a;
    asm("{ .reg .u64 t; cvta.to.shared.u64 t, %1; cvt.u32.u64 %0, t; }" : "=r"(a) : "l"(p));
    return a;
}
__device__ __forceinline__ float f2tf32(float x) {
    uint32_t u;
    asm("cvt.rn.tf32.f32 %0, %1;" : "=r"(u) : "f"(x));
    return __uint_as_float(u);
}
__device__ __forceinline__ uint32_t tf32bits(float x) {
    uint32_t u;
    asm("cvt.rn.tf32.f32 %0, %1;" : "=r"(u) : "f"(x));
    return u;
}

#define CP_ASYNC16(dst, src) \
    asm volatile("cp.async.cg.shared.global [%0], [%1], 16;" :: "r"(dst), "l"(src) : "memory")
#define CP_COMMIT() asm volatile("cp.async.commit_group;" ::: "memory")
#define CP_WAIT1()  asm volatile("cp.async.wait_group 1;" ::: "memory")
#define CP_WAIT0()  asm volatile("cp.async.wait_group 0;" ::: "memory")

// ldmatrix x4: four 8x4-b32 matrices; lane l of matrix m <- (row l/4, col l%4)
#define LDSM4(r0, r1, r2, r3, addr) \
    asm volatile("ldmatrix.sync.aligned.m8n8.x4.shared.b16 {%0,%1,%2,%3}, [%4];" \
        : "=r"(r0), "=r"(r1), "=r"(r2), "=r"(r3) : "r"(addr))

// m16n8k8 tf32 mma, fp32 accumulate
__device__ __forceinline__ void mma_tf32(float d[4], const uint32_t a[4],
                                         uint32_t b0, uint32_t b1) {
    asm volatile("mma.sync.aligned.m16n8k8.row.col.f32.tf32.tf32.f32 "
        "{%0,%1,%2,%3}, {%4,%5,%6,%7}, {%8,%9}, {%0,%1,%2,%3};"
        : "+f"(d[0]), "+f"(d[1]), "+f"(d[2]), "+f"(d[3])
        : "r"(a[0]), "r"(a[1]), "r"(a[2]), "r"(a[3]), "r"(b0), "r"(b1));
}

// C-fragment -> A-fragment butterfly with tf32 rounding.
__device__ __forceinline__ void c2a(const float c[4], uint32_t a[4]) {
    const int lane = threadIdx.x & 31;
    const int cg = lane & 3, base = lane & ~3;
    const int sLo = base + (cg >> 1);
    const int sHi = base + 2 + (cg >> 1);
    float e, o;
    e = __shfl_sync(0xffffffffu, c[0], sLo); o = __shfl_sync(0xffffffffu, c[1], sLo);
    const float lo_r = (cg & 1) ? o : e;
    e = __shfl_sync(0xffffffffu, c[0], sHi); o = __shfl_sync(0xffffffffu, c[1], sHi);
    const float hi_r = (cg & 1) ? o : e;
    e = __shfl_sync(0xffffffffu, c[2], sLo); o = __shfl_sync(0xffffffffu, c[3], sLo);
    const float lo_s = (cg & 1) ? o : e;
    e = __shfl_sync(0xffffffffu, c[2], sHi); o = __shfl_sync(0xffffffffu, c[3], sHi);
    const float hi_s = (cg & 1) ? o : e;
    a[0] = tf32bits(lo_r); a[1] = tf32bits(lo_s);
    a[2] = tf32bits(hi_r); a[3] = tf32bits(hi_s);
}

// ---------------------------------------------------------------------------
// Fused QKV projection (grid.z selects Q/K/V); tf32-rounded; V stored [bh][d][s]
// ---------------------------------------------------------------------------
__global__ __launch_bounds__(256) void proj_kernel(
    const float* __restrict__ Xq, const float* __restrict__ Xk, const float* __restrict__ Xv,
    const float* __restrict__ Wq, const float* __restrict__ Wk, const float* __restrict__ Wv,
    const float* __restrict__ bq, const float* __restrict__ bk, const float* __restrict__ bv)
{
    __shared__ float Xs[64*PITCH];
    __shared__ float Ws[64*PITCH];

    const int which = blockIdx.z;
    const float* X    = (which == 0) ? Xq : (which == 1) ? Xk : Xv;
    const float* W    = (which == 0) ? Wq : (which == 1) ? Wk : Wv;
    const float* bias = (which == 0) ? bq : (which == 1) ? bk : bv;

    const int bh = blockIdx.y;
    const int b  = bh >> 4, h = bh & 15;
    const int s0 = blockIdx.x * 64;
    const int tid = threadIdx.x;
    const int ty = tid >> 4, tx = tid & 15;

    for (int idx = tid; idx < 64*64; idx += 256) {
        const int r = idx >> 6, k = idx & 63;
        Xs[r*PITCH + k] = X[(size_t)(b*SS + s0 + r)*DMODEL + h*DD + k];
        Ws[r*PITCH + k] = W[idx];
    }
    __syncthreads();

    float acc[4][4] = {};
#pragma unroll
    for (int ks = 0; ks < 16; ks++) {
        float4 xa[4], wb[4];
#pragma unroll
        for (int i = 0; i < 4; i++) xa[i] = *(const float4*)&Xs[(ty + i*16)*PITCH + ks*4];
#pragma unroll
        for (int ii = 0; ii < 4; ii++) wb[ii] = *(const float4*)&Ws[(tx + ii*16)*PITCH + ks*4];
#pragma unroll
        for (int i = 0; i < 4; i++)
#pragma unroll
            for (int ii = 0; ii < 4; ii++)
                acc[i][ii] += xa[i].x*wb[ii].x + xa[i].y*wb[ii].y
                            + xa[i].z*wb[ii].z + xa[i].w*wb[ii].w;
    }

    if (which != 2) {
        float* out = (which == 0) ? g_Qp : g_Kp;
#pragma unroll
        for (int i = 0; i < 4; i++) {
            const int r = ty + i*16;
#pragma unroll
            for (int ii = 0; ii < 4; ii++) {
                const int o = tx + ii*16;
                out[((size_t)bh*SS + s0 + r)*DD + o] = f2tf32(acc[i][ii] + bias[o]);
            }
        }
    } else {
        __syncthreads();
#pragma unroll
        for (int i = 0; i < 4; i++)
#pragma unroll
            for (int ii = 0; ii < 4; ii++)
                Xs[(ty + i*16)*PITCH + tx + ii*16] = f2tf32(acc[i][ii] + bias[tx + ii*16]);
        __syncthreads();
        for (int idx = tid; idx < 64*64; idx += 256) {
            const int d = idx >> 6, sl = idx & 63;
            g_Vt[((size_t)(bh*DD + d))*SS + s0 + sl] = Xs[sl*PITCH + d];
        }
    }
}

// ---------------------------------------------------------------------------
// Wo -> tf32-rounded copy
// ---------------------------------------------------------------------------
__global__ __launch_bounds__(256) void round_wo(const float* __restrict__ W)
{
    const int i = blockIdx.x * 256 + threadIdx.x;   // over float4s
    float4 v = ((const float4*)W)[i];
    v.x = f2tf32(v.x); v.y = f2tf32(v.y); v.z = f2tf32(v.z); v.w = f2tf32(v.w);
    ((float4*)g_Wr)[i] = v;
}

// ---------------------------------------------------------------------------
// Flash attention: 8x1 warp layout (warp = 16 q-rows x all 64 keys/dims),
// 64-key tiles, 32 iters, 2 CTAs/SM.
// ---------------------------------------------------------------------------
#define AQ  0
#define AK0 8704
#define AK1 13056
#define AV0 17408
#define AV1 21760
#define ATTN_SMEM (26112*4)   // 104448 B -> 2 CTAs/SM

__global__ __launch_bounds__(256, 2) void attn_mma()
{
    extern __shared__ float sm[];
    const uint32_t smu = smem_to_u32(sm);

    const int bh = blockIdx.y, b = bh >> 4, h = bh & 15;
    const int s0 = blockIdx.x * 128;
    const int tid = threadIdx.x, lane = tid & 31, wid = tid >> 5;
    const int gid = lane >> 2, tig = lane & 3;
    const int lm = lane >> 3, lg = lane & 7;

    const float* __restrict__ Qp = g_Qp + (size_t)bh*SS*DD;
    const float* __restrict__ Kp = g_Kp + (size_t)bh*SS*DD;
    const float* __restrict__ Vp = g_Vt + (size_t)bh*DD*SS;

    // ldmatrix per-thread addresses (bytes)
    const uint32_t qbase = smu + ((AQ + (wid*16 + (lm & 1)*8 + lg)*PITCH + (lm >> 1)*4) << 2);
    const uint32_t krel  = (((lm >> 1)*8 + lg)*PITCH + (lm & 1)*4) << 2;  // rows=keys
    const uint32_t vrel  = krel;                                           // rows=d

    // group 0: Q + K tile0 + V tile0
    for (int i = tid; i < 2048; i += 256) {
        const int row = i >> 4, c4 = i & 15;
        CP_ASYNC16(smu + (AQ + row*PITCH + c4*4)*4, Qp + (size_t)(s0+row)*DD + c4*4);
    }
    for (int i = tid; i < 1024; i += 256) {
        const int row = i >> 4, c4 = i & 15;
        CP_ASYNC16(smu + (AK0 + row*PITCH + c4*4)*4, Kp + (size_t)row*DD + c4*4);
        CP_ASYNC16(smu + (AV0 + row*PITCH + c4*4)*4, Vp + (size_t)row*SS + c4*4);
    }
    CP_COMMIT();

    float Oc[8][4] = {};
    float rsum[2] = {};

#pragma unroll 1
    for (int n = 0; n < 32; n++) {
        const int bf = n & 1;
        const int KO = bf ? AK1 : AK0, VO = bf ? AV1 : AV0;
        __syncthreads();
        if (n < 31) {
            const int KO2 = bf ? AK0 : AK1, VO2 = bf ? AV0 : AV1;
            for (int i = tid; i < 1024; i += 256) {
                const int row = i >> 4, c4 = i & 15;
                CP_ASYNC16(smu + (KO2 + row*PITCH + c4*4)*4,
                           Kp + (size_t)((n+1)*64 + row)*DD + c4*4);
                CP_ASYNC16(smu + (VO2 + row*PITCH + c4*4)*4,
                           Vp + (size_t)row*SS + (n+1)*64 + c4*4);
            }
            CP_COMMIT();
            CP_WAIT1();
        } else {
            CP_WAIT0();
        }
        __syncthreads();

        const uint32_t kbase = smu + (KO << 2) + krel;
        const uint32_t vbase = smu + (VO << 2) + vrel;

        // ---- S = Q @ K^T (16 rows x 64 keys) ----
        float Sc[8][4] = {};
#pragma unroll
        for (int kk = 0; kk < 8; kk++) {
            uint32_t qa[4];
            LDSM4(qa[0], qa[1], qa[2], qa[3], qbase + kk*32);
#pragma unroll
            for (int ntp = 0; ntp < 4; ntp++) {
                uint32_t b00, b01, b10, b11;
                LDSM4(b00, b01, b10, b11, kbase + ntp*(16*PITCH*4) + kk*32);
                mma_tf32(Sc[2*ntp],   qa, b00, b01);
                mma_tf32(Sc[2*ntp+1], qa, b10, b11);
            }
        }

        // ---- softmax (in registers; scores tiny, no max-shift needed) ----
#pragma unroll
        for (int nt = 0; nt < 8; nt++) {
            const float p0 = __expf(Sc[nt][0]*SCALE);
            const float p1 = __expf(Sc[nt][1]*SCALE);
            const float p2 = __expf(Sc[nt][2]*SCALE);
            const float p3 = __expf(Sc[nt][3]*SCALE);
            rsum[0] += p0 + p1;
            rsum[1] += p2 + p3;
            Sc[nt][0] = p0; Sc[nt][1] = p1;
            Sc[nt][2] = p2; Sc[nt][3] = p3;
        }

        // ---- O += P @ V (16 rows x 64 dims) ----
#pragma unroll
        for (int kk = 0; kk < 8; kk++) {
            uint32_t pa[4];
            c2a(Sc[kk], pa);
#pragma unroll
            for (int nop = 0; nop < 4; nop++) {
                uint32_t b00, b01, b10, b11;
                LDSM4(b00, b01, b10, b11, vbase + nop*(16*PITCH*4) + kk*32);
                mma_tf32(Oc[2*nop],   pa, b00, b01);
                mma_tf32(Oc[2*nop+1], pa, b10, b11);
            }
        }
    }

    // ---- epilogue: quad-reduce rowsums, direct store (warp owns its rows) ----
#pragma unroll
    for (int i = 0; i < 2; i++) {
        rsum[i] += __shfl_xor_sync(0xffffffffu, rsum[i], 1);
        rsum[i] += __shfl_xor_sync(0xffffffffu, rsum[i], 2);
    }
    const float inv0 = 1.0f / rsum[0];
    const float inv1 = 1.0f / rsum[1];
    const int r0 = wid*16 + gid;
    float* dst0 = g_O + (size_t)(b*SS + s0 + r0)*DMODEL + h*DD;
    float* dst1 = g_O + (size_t)(b*SS + s0 + r0 + 8)*DMODEL + h*DD;
#pragma unroll
    for (int nt = 0; nt < 8; nt++) {
        const int c = nt*8 + 2*tig;
        *(float2*)(dst0 + c) = make_float2(f2tf32(Oc[nt][0]*inv0), f2tf32(Oc[nt][1]*inv0));
        *(float2*)(dst1 + c) = make_float2(f2tf32(Oc[nt][2]*inv1), f2tf32(Oc[nt][3]*inv1));
    }
}

// ---------------------------------------------------------------------------
// Output projection: tile M=128 x N=64, 8x1 warps, 2 CTAs/SM
// ---------------------------------------------------------------------------
#define PA0 0
#define PA1 8704
#define PW0 17408
#define PW1 21760
#define OUTP_SMEM (26112*4)   // 104448 B

__global__ __launch_bounds__(256, 2) void outproj_mma(
    const float* __restrict__ bo, float* __restrict__ out)
{
    extern __shared__ float sm[];
    const uint32_t smu = smem_to_u32(sm);

    const int n0 = blockIdx.x * 64, m0 = blockIdx.y * 128;
    const int tid = threadIdx.x, lane = tid & 31, wid = tid >> 5;
    const int gid = lane >> 2, tig = lane & 3;
    const int lm = lane >> 3, lg = lane & 7;

    const uint32_t arel = ((wid*16 + (lm & 1)*8 + lg)*PITCH + (lm >> 1)*4) << 2;
    const uint32_t wrel = (((lm >> 1)*8 + lg)*PITCH + (lm & 1)*4) << 2;

    for (int i = tid; i < 2048; i += 256) {
        const int row = i >> 4, c4 = i & 15;
        CP_ASYNC16(smu + (PA0 + row*PITCH + c4*4)*4, g_O + (size_t)(m0+row)*DMODEL + c4*4);
    }
    for (int i = tid; i < 1024; i += 256) {
        const int row = i >> 4, c4 = i & 15;
        CP_ASYNC16(smu + (PW0 + row*PITCH + c4*4)*4, g_Wr + (size_t)(n0+row)*DMODEL + c4*4);
    }
    CP_COMMIT();

    float Oc[8][4] = {};

#pragma unroll 1
    for (int kt = 0; kt < 16; kt++) {
        const int bf = kt & 1;
        const int AO = bf ? PA1 : PA0, WO = bf ? PW1 : PW0;
        __syncthreads();
        if (kt < 15) {
            const int AO2 = bf ? PA0 : PA1, WO2 = bf ? PW0 : PW1;
            for (int i = tid; i < 2048; i += 256) {
                const int row = i >> 4, c4 = i & 15;
                CP_ASYNC16(smu + (AO2 + row*PITCH + c4*4)*4,
                           g_O + (size_t)(m0+row)*DMODEL + (kt+1)*64 + c4*4);
            }
            for (int i = tid; i < 1024; i += 256) {
                const int row = i >> 4, c4 = i & 15;
                CP_ASYNC16(smu + (WO2 + row*PITCH + c4*4)*4,
                           g_Wr + (size_t)(n0+row)*DMODEL + (kt+1)*64 + c4*4);
            }
            CP_COMMIT();
            CP_WAIT1();
        } else {
            CP_WAIT0();
        }
        __syncthreads();

        const uint32_t abase = smu + (AO << 2) + arel;
        const uint32_t wbase = smu + (WO << 2) + wrel;
#pragma unroll
        for (int kk = 0; kk < 8; kk++) {
            uint32_t aa[4];
            LDSM4(aa[0], aa[1], aa[2], aa[3], abase + kk*32);
#pragma unroll
            for (int ntp = 0; ntp < 4; ntp++) {
                uint32_t b00, b01, b10, b11;
                LDSM4(b00, b01, b10, b11, wbase + ntp*(16*PITCH*4) + kk*32);
                mma_tf32(Oc[2*ntp],   aa, b00, b01);
                mma_tf32(Oc[2*ntp+1], aa, b10, b11);
            }
        }
    }

    // epilogue: direct store + bias
    const int r0 = m0 + wid*16 + gid;
#pragma unroll
    for (int nt = 0; nt < 8; nt++) {
        const int c0 = n0 + nt*8 + 2*tig;
        const float bv0 = bo[c0], bv1 = bo[c0+1];
        *(float2*)(out + (size_t)r0*DMODEL + c0) =
            make_float2(Oc[nt][0] + bv0, Oc[nt][1] + bv1);
        *(float2*)(out + (size_t)(r0+8)*DMODEL + c0) =
            make_float2(Oc[nt][2] + bv0, Oc[nt][3] + bv1);
    }
}

// ---------------------------------------------------------------------------
extern "C" void kernel_launch(void* const* d_in, const int* in_sizes, int n_in,
                              void* d_out, int out_size)
{
    const float* q  = (const float*)d_in[0];
    const float* k  = (const float*)d_in[1];
    const float* v  = (const float*)d_in[2];
    // d_in[3] = mask (no-op in reference)
    const float* Wq = (const float*)d_in[4];
    const float* bq = (const float*)d_in[5];
    const float* Wk = (const float*)d_in[6];
    const float* bk = (const float*)d_in[7];
    const float* Wv = (const float*)d_in[8];
    const float* bv = (const float*)d_in[9];
    const float* Wo = (const float*)d_in[10];
    const float* bo = (const float*)d_in[11];
    float* out = (float*)d_out;

    cudaFuncSetAttribute(attn_mma,    cudaFuncAttributeMaxDynamicSharedMemorySize, ATTN_SMEM);
    cudaFuncSetAttribute(outproj_mma, cudaFuncAttributeMaxDynamicSharedMemorySize, OUTP_SMEM);

    dim3 blk(256);
    round_wo<<<DMODEL*DMODEL/4/256, blk>>>(Wo);
    proj_kernel<<<dim3(SS/64, BB*HH, 3), blk>>>(q, k, v, Wq, Wk, Wv, bq, bk, bv);

    attn_mma<<<dim3(SS/128, BB*HH), blk, ATTN_SMEM>>>();

    outproj_mma<<<dim3(DMODEL/64, BB*SS/128), blk, OUTP_SMEM>>>(bo, out);
}

// round 17
// speedup vs baseline: 1.0875x; 1.0875x over previous
#include <cuda_runtime.h>
#include <cstdint>

#define BB 4
#define SS 2048
#define HH 16
#define DD 64
#define DMODEL 1024
#define PITCH 68            // smem row pitch (floats): 68%32=4 -> conflict-free ldmatrix phases
#define SCALE (1.0f/32.0f)  // score / (D/2)

// ---------------- scratch (no runtime allocation allowed) -------------------
__device__ float g_Qp[BB*HH*SS*DD];   // [bh][s][d], tf32-rounded
__device__ float g_Kp[BB*HH*SS*DD];   // [bh][s][d], tf32-rounded
__device__ float g_Vt[BB*HH*DD*SS];   // [bh][d][s] transposed, tf32-rounded
__device__ float g_O [BB*SS*DMODEL];  // [b][s][h*D+d], tf32-rounded
__device__ float g_Wr[DMODEL*DMODEL]; // Wo tf32-rounded

// ---------------- helpers ---------------------------------------------------
__device__ __forceinline__ uint32_t smem_to_u32(const void* p) {
    uint32_t a;
    asm("{ .reg .u64 t; cvta.to.shared.u64 t, %1; cvt.u32.u64 %0, t; }" : "=r"(a) : "l"(p));
    return a;
}
__device__ __forceinline__ float f2tf32(float x) {
    uint32_t u;
    asm("cvt.rn.tf32.f32 %0, %1;" : "=r"(u) : "f"(x));
    return __uint_as_float(u);
}
__device__ __forceinline__ uint32_t tf32bits(float x) {
    uint32_t u;
    asm("cvt.rn.tf32.f32 %0, %1;" : "=r"(u) : "f"(x));
    return u;
}

#define CP_ASYNC16(dst, src) \
    asm volatile("cp.async.cg.shared.global [%0], [%1], 16;" :: "r"(dst), "l"(src) : "memory")
#define CP_COMMIT() asm volatile("cp.async.commit_group;" ::: "memory")
#define CP_WAIT1()  asm volatile("cp.async.wait_group 1;" ::: "memory")
#define CP_WAIT0()  asm volatile("cp.async.wait_group 0;" ::: "memory")

// ldmatrix x4: four 8x4-b32 matrices; lane l of matrix m <- (row l/4, col l%4)
#define LDSM4(r0, r1, r2, r3, addr) \
    asm volatile("ldmatrix.sync.aligned.m8n8.x4.shared.b16 {%0,%1,%2,%3}, [%4];" \
        : "=r"(r0), "=r"(r1), "=r"(r2), "=r"(r3) : "r"(addr))

// m16n8k8 tf32 mma, fp32 accumulate
__device__ __forceinline__ void mma_tf32(float d[4], const uint32_t a[4],
                                         uint32_t b0, uint32_t b1) {
    asm volatile("mma.sync.aligned.m16n8k8.row.col.f32.tf32.tf32.f32 "
        "{%0,%1,%2,%3}, {%4,%5,%6,%7}, {%8,%9}, {%0,%1,%2,%3};"
        : "+f"(d[0]), "+f"(d[1]), "+f"(d[2]), "+f"(d[3])
        : "r"(a[0]), "r"(a[1]), "r"(a[2]), "r"(a[3]), "r"(b0), "r"(b1));
}

// C-fragment -> A-fragment butterfly with tf32 rounding.
__device__ __forceinline__ void c2a(const float c[4], uint32_t a[4]) {
    const int lane = threadIdx.x & 31;
    const int cg = lane & 3, base = lane & ~3;
    const int sLo = base + (cg >> 1);
    const int sHi = base + 2 + (cg >> 1);
    float e, o;
    e = __shfl_sync(0xffffffffu, c[0], sLo); o = __shfl_sync(0xffffffffu, c[1], sLo);
    const float lo_r = (cg & 1) ? o : e;
    e = __shfl_sync(0xffffffffu, c[0], sHi); o = __shfl_sync(0xffffffffu, c[1], sHi);
    const float hi_r = (cg & 1) ? o : e;
    e = __shfl_sync(0xffffffffu, c[2], sLo); o = __shfl_sync(0xffffffffu, c[3], sLo);
    const float lo_s = (cg & 1) ? o : e;
    e = __shfl_sync(0xffffffffu, c[2], sHi); o = __shfl_sync(0xffffffffu, c[3], sHi);
    const float hi_s = (cg & 1) ? o : e;
    a[0] = tf32bits(lo_r); a[1] = tf32bits(lo_s);
    a[2] = tf32bits(hi_r); a[3] = tf32bits(hi_s);
}

// ---------------------------------------------------------------------------
// Fused QKV projection (grid.z selects Q/K/V); tf32-rounded; V stored [bh][d][s]
// ---------------------------------------------------------------------------
__global__ __launch_bounds__(256) void proj_kernel(
    const float* __restrict__ Xq, const float* __restrict__ Xk, const float* __restrict__ Xv,
    const float* __restrict__ Wq, const float* __restrict__ Wk, const float* __restrict__ Wv,
    const float* __restrict__ bq, const float* __restrict__ bk, const float* __restrict__ bv)
{
    __shared__ float Xs[64*PITCH];
    __shared__ float Ws[64*PITCH];

    const int which = blockIdx.z;
    const float* X    = (which == 0) ? Xq : (which == 1) ? Xk : Xv;
    const float* W    = (which == 0) ? Wq : (which == 1) ? Wk : Wv;
    const float* bias = (which == 0) ? bq : (which == 1) ? bk : bv;

    const int bh = blockIdx.y;
    const int b  = bh >> 4, h = bh & 15;
    const int s0 = blockIdx.x * 64;
    const int tid = threadIdx.x;
    const int ty = tid >> 4, tx = tid & 15;

    for (int idx = tid; idx < 64*64; idx += 256) {
        const int r = idx >> 6, k = idx & 63;
        Xs[r*PITCH + k] = X[(size_t)(b*SS + s0 + r)*DMODEL + h*DD + k];
        Ws[r*PITCH + k] = W[idx];
    }
    __syncthreads();

    float acc[4][4] = {};
#pragma unroll
    for (int ks = 0; ks < 16; ks++) {
        float4 xa[4], wb[4];
#pragma unroll
        for (int i = 0; i < 4; i++) xa[i] = *(const float4*)&Xs[(ty + i*16)*PITCH + ks*4];
#pragma unroll
        for (int ii = 0; ii < 4; ii++) wb[ii] = *(const float4*)&Ws[(tx + ii*16)*PITCH + ks*4];
#pragma unroll
        for (int i = 0; i < 4; i++)
#pragma unroll
            for (int ii = 0; ii < 4; ii++)
                acc[i][ii] += xa[i].x*wb[ii].x + xa[i].y*wb[ii].y
                            + xa[i].z*wb[ii].z + xa[i].w*wb[ii].w;
    }

    if (which != 2) {
        float* out = (which == 0) ? g_Qp : g_Kp;
#pragma unroll
        for (int i = 0; i < 4; i++) {
            const int r = ty + i*16;
#pragma unroll
            for (int ii = 0; ii < 4; ii++) {
                const int o = tx + ii*16;
                out[((size_t)bh*SS + s0 + r)*DD + o] = f2tf32(acc[i][ii] + bias[o]);
            }
        }
    } else {
        __syncthreads();
#pragma unroll
        for (int i = 0; i < 4; i++)
#pragma unroll
            for (int ii = 0; ii < 4; ii++)
                Xs[(ty + i*16)*PITCH + tx + ii*16] = f2tf32(acc[i][ii] + bias[tx + ii*16]);
        __syncthreads();
        for (int idx = tid; idx < 64*64; idx += 256) {
            const int d = idx >> 6, sl = idx & 63;
            g_Vt[((size_t)(bh*DD + d))*SS + s0 + sl] = Xs[sl*PITCH + d];
        }
    }
}

// ---------------------------------------------------------------------------
// Wo -> tf32-rounded copy
// ---------------------------------------------------------------------------
__global__ __launch_bounds__(256) void round_wo(const float* __restrict__ W)
{
    const int i = blockIdx.x * 256 + threadIdx.x;   // over float4s
    float4 v = ((const float4*)W)[i];
    v.x = f2tf32(v.x); v.y = f2tf32(v.y); v.z = f2tf32(v.z); v.w = f2tf32(v.w);
    ((float4*)g_Wr)[i] = v;
}

// ---------------------------------------------------------------------------
// Flash attention: 128 threads, 4 warps x 32 q-rows (B-fragments reused x2),
// 64-key tiles, 32 iters, 2 CTAs/SM.
// ---------------------------------------------------------------------------
#define AQ  0
#define AK0 8704
#define AK1 13056
#define AV0 17408
#define AV1 21760
#define ATTN_SMEM (26112*4)   // 104448 B -> 2 CTAs/SM

__global__ __launch_bounds__(128, 2) void attn_mma()
{
    extern __shared__ float sm[];
    const uint32_t smu = smem_to_u32(sm);

    const int bh = blockIdx.y, b = bh >> 4, h = bh & 15;
    const int s0 = blockIdx.x * 128;
    const int tid = threadIdx.x, lane = tid & 31, wid = tid >> 5;
    const int gid = lane >> 2, tig = lane & 3;
    const int lm = lane >> 3, lg = lane & 7;

    const float* __restrict__ Qp = g_Qp + (size_t)bh*SS*DD;
    const float* __restrict__ Kp = g_Kp + (size_t)bh*SS*DD;
    const float* __restrict__ Vp = g_Vt + (size_t)bh*DD*SS;

    // ldmatrix per-thread addresses (bytes); warp owns rows [wid*32, wid*32+32)
    uint32_t qbase[2];
#pragma unroll
    for (int mt = 0; mt < 2; mt++)
        qbase[mt] = smu + ((AQ + (wid*32 + mt*16 + (lm & 1)*8 + lg)*PITCH + (lm >> 1)*4) << 2);
    const uint32_t krel = (((lm >> 1)*8 + lg)*PITCH + (lm & 1)*4) << 2;  // rows=keys
    const uint32_t vrel = krel;                                           // rows=d

    // group 0: Q + K tile0 + V tile0
    for (int i = tid; i < 2048; i += 128) {
        const int row = i >> 4, c4 = i & 15;
        CP_ASYNC16(smu + (AQ + row*PITCH + c4*4)*4, Qp + (size_t)(s0+row)*DD + c4*4);
    }
    for (int i = tid; i < 1024; i += 128) {
        const int row = i >> 4, c4 = i & 15;
        CP_ASYNC16(smu + (AK0 + row*PITCH + c4*4)*4, Kp + (size_t)row*DD + c4*4);
        CP_ASYNC16(smu + (AV0 + row*PITCH + c4*4)*4, Vp + (size_t)row*SS + c4*4);
    }
    CP_COMMIT();

    float Oc[2][8][4] = {};
    float rsum[4] = {};

#pragma unroll 1
    for (int n = 0; n < 32; n++) {
        const int bf = n & 1;
        const int KO = bf ? AK1 : AK0, VO = bf ? AV1 : AV0;
        __syncthreads();
        if (n < 31) {
            const int KO2 = bf ? AK0 : AK1, VO2 = bf ? AV0 : AV1;
            for (int i = tid; i < 1024; i += 128) {
                const int row = i >> 4, c4 = i & 15;
                CP_ASYNC16(smu + (KO2 + row*PITCH + c4*4)*4,
                           Kp + (size_t)((n+1)*64 + row)*DD + c4*4);
                CP_ASYNC16(smu + (VO2 + row*PITCH + c4*4)*4,
                           Vp + (size_t)row*SS + (n+1)*64 + c4*4);
            }
            CP_COMMIT();
            CP_WAIT1();
        } else {
            CP_WAIT0();
        }
        __syncthreads();

        const uint32_t kbase = smu + (KO << 2) + krel;
        const uint32_t vbase = smu + (VO << 2) + vrel;

        // ---- S = Q @ K^T (32 rows x 64 keys) ----
        float Sc[2][8][4] = {};
#pragma unroll
        for (int kk = 0; kk < 8; kk++) {
            uint32_t qa[2][4];
            LDSM4(qa[0][0], qa[0][1], qa[0][2], qa[0][3], qbase[0] + kk*32);
            LDSM4(qa[1][0], qa[1][1], qa[1][2], qa[1][3], qbase[1] + kk*32);
#pragma unroll
            for (int ntp = 0; ntp < 4; ntp++) {
                uint32_t b00, b01, b10, b11;
                LDSM4(b00, b01, b10, b11, kbase + ntp*(16*PITCH*4) + kk*32);
                mma_tf32(Sc[0][2*ntp],   qa[0], b00, b01);
                mma_tf32(Sc[1][2*ntp],   qa[1], b00, b01);
                mma_tf32(Sc[0][2*ntp+1], qa[0], b10, b11);
                mma_tf32(Sc[1][2*ntp+1], qa[1], b10, b11);
            }
        }

        // ---- softmax (in registers; scores tiny, no max-shift needed) ----
#pragma unroll
        for (int mt = 0; mt < 2; mt++)
#pragma unroll
            for (int nt = 0; nt < 8; nt++) {
                const float p0 = __expf(Sc[mt][nt][0]*SCALE);
                const float p1 = __expf(Sc[mt][nt][1]*SCALE);
                const float p2 = __expf(Sc[mt][nt][2]*SCALE);
                const float p3 = __expf(Sc[mt][nt][3]*SCALE);
                rsum[mt*2+0] += p0 + p1;
                rsum[mt*2+1] += p2 + p3;
                Sc[mt][nt][0] = p0; Sc[mt][nt][1] = p1;
                Sc[mt][nt][2] = p2; Sc[mt][nt][3] = p3;
            }

        // ---- O += P @ V (32 rows x 64 dims) ----
#pragma unroll
        for (int kk = 0; kk < 8; kk++) {
            uint32_t pa0[4], pa1[4];
            c2a(Sc[0][kk], pa0);
            c2a(Sc[1][kk], pa1);
#pragma unroll
            for (int nop = 0; nop < 4; nop++) {
                uint32_t b00, b01, b10, b11;
                LDSM4(b00, b01, b10, b11, vbase + nop*(16*PITCH*4) + kk*32);
                mma_tf32(Oc[0][2*nop],   pa0, b00, b01);
                mma_tf32(Oc[1][2*nop],   pa1, b00, b01);
                mma_tf32(Oc[0][2*nop+1], pa0, b10, b11);
                mma_tf32(Oc[1][2*nop+1], pa1, b10, b11);
            }
        }
    }

    // ---- epilogue: quad-reduce rowsums, direct store (warp owns its rows) ----
#pragma unroll
    for (int i = 0; i < 4; i++) {
        rsum[i] += __shfl_xor_sync(0xffffffffu, rsum[i], 1);
        rsum[i] += __shfl_xor_sync(0xffffffffu, rsum[i], 2);
    }
#pragma unroll
    for (int mt = 0; mt < 2; mt++) {
        const float inv0 = 1.0f / rsum[mt*2+0];
        const float inv1 = 1.0f / rsum[mt*2+1];
        const int r0 = wid*32 + mt*16 + gid;
        float* dst0 = g_O + (size_t)(b*SS + s0 + r0)*DMODEL + h*DD;
        float* dst1 = g_O + (size_t)(b*SS + s0 + r0 + 8)*DMODEL + h*DD;
#pragma unroll
        for (int nt = 0; nt < 8; nt++) {
            const int c = nt*8 + 2*tig;
            *(float2*)(dst0 + c) = make_float2(f2tf32(Oc[mt][nt][0]*inv0), f2tf32(Oc[mt][nt][1]*inv0));
            *(float2*)(dst1 + c) = make_float2(f2tf32(Oc[mt][nt][2]*inv1), f2tf32(Oc[mt][nt][3]*inv1));
        }
    }
}

// ---------------------------------------------------------------------------
// Output projection: 128 threads, 4 warps x 32 rows, tile M=128 x N=64, 2 CTAs/SM
// ---------------------------------------------------------------------------
#define PA0 0
#define PA1 8704
#define PW0 17408
#define PW1 21760
#define OUTP_SMEM (26112*4)   // 104448 B

__global__ __launch_bounds__(128, 2) void outproj_mma(
    const float* __restrict__ bo, float* __restrict__ out)
{
    extern __shared__ float sm[];
    const uint32_t smu = smem_to_u32(sm);

    const int n0 = blockIdx.x * 64, m0 = blockIdx.y * 128;
    const int tid = threadIdx.x, lane = tid & 31, wid = tid >> 5;
    const int gid = lane >> 2, tig = lane & 3;
    const int lm = lane >> 3, lg = lane & 7;

    uint32_t arel[2];
#pragma unroll
    for (int mt = 0; mt < 2; mt++)
        arel[mt] = ((wid*32 + mt*16 + (lm & 1)*8 + lg)*PITCH + (lm >> 1)*4) << 2;
    const uint32_t wrel = (((lm >> 1)*8 + lg)*PITCH + (lm & 1)*4) << 2;

    for (int i = tid; i < 2048; i += 128) {
        const int row = i >> 4, c4 = i & 15;
        CP_ASYNC16(smu + (PA0 + row*PITCH + c4*4)*4, g_O + (size_t)(m0+row)*DMODEL + c4*4);
    }
    for (int i = tid; i < 1024; i += 128) {
        const int row = i >> 4, c4 = i & 15;
        CP_ASYNC16(smu + (PW0 + row*PITCH + c4*4)*4, g_Wr + (size_t)(n0+row)*DMODEL + c4*4);
    }
    CP_COMMIT();

    float Oc[2][8][4] = {};

#pragma unroll 1
    for (int kt = 0; kt < 16; kt++) {
        const int bf = kt & 1;
        const int AO = bf ? PA1 : PA0, WO = bf ? PW1 : PW0;
        __syncthreads();
        if (kt < 15) {
            const int AO2 = bf ? PA0 : PA1, WO2 = bf ? PW0 : PW1;
            for (int i = tid; i < 2048; i += 128) {
                const int row = i >> 4, c4 = i & 15;
                CP_ASYNC16(smu + (AO2 + row*PITCH + c4*4)*4,
                           g_O + (size_t)(m0+row)*DMODEL + (kt+1)*64 + c4*4);
            }
            for (int i = tid; i < 1024; i += 128) {
                const int row = i >> 4, c4 = i & 15;
                CP_ASYNC16(smu + (WO2 + row*PITCH + c4*4)*4,
                           g_Wr + (size_t)(n0+row)*DMODEL + (kt+1)*64 + c4*4);
            }
            CP_COMMIT();
            CP_WAIT1();
        } else {
            CP_WAIT0();
        }
        __syncthreads();

        const uint32_t abase0 = smu + (AO << 2) + arel[0];
        const uint32_t abase1 = smu + (AO << 2) + arel[1];
        const uint32_t wbase  = smu + (WO << 2) + wrel;
#pragma unroll
        for (int kk = 0; kk < 8; kk++) {
            uint32_t aa[2][4];
            LDSM4(aa[0][0], aa[0][1], aa[0][2], aa[0][3], abase0 + kk*32);
            LDSM4(aa[1][0], aa[1][1], aa[1][2], aa[1][3], abase1 + kk*32);
#pragma unroll
            for (int ntp = 0; ntp < 4; ntp++) {
                uint32_t b00, b01, b10, b11;
                LDSM4(b00, b01, b10, b11, wbase + ntp*(16*PITCH*4) + kk*32);
                mma_tf32(Oc[0][2*ntp],   aa[0], b00, b01);
                mma_tf32(Oc[1][2*ntp],   aa[1], b00, b01);
                mma_tf32(Oc[0][2*ntp+1], aa[0], b10, b11);
                mma_tf32(Oc[1][2*ntp+1], aa[1], b10, b11);
            }
        }
    }

    // epilogue: direct store + bias
#pragma unroll
    for (int mt = 0; mt < 2; mt++) {
        const int r0 = m0 + wid*32 + mt*16 + gid;
#pragma unroll
        for (int nt = 0; nt < 8; nt++) {
            const int c0 = n0 + nt*8 + 2*tig;
            const float bv0 = bo[c0], bv1 = bo[c0+1];
            *(float2*)(out + (size_t)r0*DMODEL + c0) =
                make_float2(Oc[mt][nt][0] + bv0, Oc[mt][nt][1] + bv1);
            *(float2*)(out + (size_t)(r0+8)*DMODEL + c0) =
                make_float2(Oc[mt][nt][2] + bv0, Oc[mt][nt][3] + bv1);
        }
    }
}

// ---------------------------------------------------------------------------
extern "C" void kernel_launch(void* const* d_in, const int* in_sizes, int n_in,
                              void* d_out, int out_size)
{
    const float* q  = (const float*)d_in[0];
    const float* k  = (const float*)d_in[1];
    const float* v  = (const float*)d_in[2];
    // d_in[3] = mask (no-op in reference)
    const float* Wq = (const float*)d_in[4];
    const float* bq = (const float*)d_in[5];
    const float* Wk = (const float*)d_in[6];
    const float* bk = (const float*)d_in[7];
    const float* Wv = (const float*)d_in[8];
    const float* bv = (const float*)d_in[9];
    const float* Wo = (const float*)d_in[10];
    const float* bo = (const float*)d_in[11];
    float* out = (float*)d_out;

    cudaFuncSetAttribute(attn_mma,    cudaFuncAttributeMaxDynamicSharedMemorySize, ATTN_SMEM);
    cudaFuncSetAttribute(outproj_mma, cudaFuncAttributeMaxDynamicSharedMemorySize, OUTP_SMEM);

    round_wo<<<DMODEL*DMODEL/4/256, 256>>>(Wo);
    proj_kernel<<<dim3(SS/64, BB*HH, 3), 256>>>(q, k, v, Wq, Wk, Wv, bq, bk, bv);

    attn_mma<<<dim3(SS/128, BB*HH), 128, ATTN_SMEM>>>();

    outproj_mma<<<dim3(DMODEL/64, BB*SS/128), 128, OUTP_SMEM>>>(bo, out);
}